// round 5
// baseline (speedup 1.0000x reference)
// NonlocalBlock on GB300 (sm_103a) — TF32 mma.sync pipeline, round 1 baseline.
//
// Pipeline (all per batch n):
//   prep:    x, weights -> tf32-rounded copies (cvt.rna, unbiased)
//   stageA:  TPG[3*128,4096] = Wcat[384,256] @ x[256,4096], BN+relu, tf32-round
//   stageB:  kv partials (split-K over S=4096 in 8 chunks), deterministic reduce
//   stageC:  O[s,d] = sum_c T[c,s]*kv[c,d]  (written flat s*128+d == "reshape")
//   stageD:  out = relu(bn4(Wzeta @ Y) + x),  Y = O reinterpreted [128][4096]
//
// GEMM core: 128x128x16 CTA tile, 256 thr (8 warps, 2x4), warp tile 64x32,
// mma.sync.m16n8k8.tf32, cp.async double-buffered, conflict-free smem pads.

#include <cuda_runtime.h>
#include <cstdint>
#include <cstddef>

#define DEVI __device__ __forceinline__

namespace {
constexpr int NB = 16;
constexpr int CH = 256;
constexpr int WD = 128;
constexpr int SP = 4096;
constexpr float BN_EPS = 1e-5f;
constexpr int KVSPLIT = 8;
constexpr int KVCHUNK = SP / KVSPLIT; // 512
}

// ---- static device scratch (allocation-free rule) ----
__device__ __align__(256) float g_xt[NB * CH * SP];        // tf32 x       (67 MB)
__device__ __align__(256) float g_wt[3 * WD * CH];         // tf32 theta/phi/g weights
__device__ __align__(256) float g_wz[CH * WD];             // tf32 zeta weights
__device__ __align__(256) float g_TPG[NB * 3 * WD * SP];   // relu(bn(conv)), tf32 (100 MB)
__device__ __align__(256) float g_kvp[NB * KVSPLIT * WD * WD]; // kv partials
__device__ __align__(256) float g_kv[NB * WD * WD];        // tf32 kv
__device__ __align__(256) float g_O[NB * SP * WD];         // tf32 O, flat s*128+d (33 MB)

// ---- helpers ----
DEVI float to_tf32(float x) {
    uint32_t u;
    asm("cvt.rna.tf32.f32 %0, %1;" : "=r"(u) : "f"(x));
    return __uint_as_float(u);
}

DEVI void cpa16(float* s, const float* g) {
    uint32_t sa = (uint32_t)__cvta_generic_to_shared(s);
    asm volatile("cp.async.cg.shared.global [%0], [%1], 16;" :: "r"(sa), "l"(g));
}
DEVI void cpa_commit()   { asm volatile("cp.async.commit_group;"); }
DEVI void cpa_wait_all() { asm volatile("cp.async.wait_group 0;"); }
DEVI void cpa_wait_one() { asm volatile("cp.async.wait_group 1;"); }

DEVI void mma8(float* d, const uint32_t* a, const uint32_t* b) {
    asm volatile(
        "mma.sync.aligned.m16n8k8.row.col.f32.tf32.tf32.f32 "
        "{%0,%1,%2,%3}, {%4,%5,%6,%7}, {%8,%9}, {%0,%1,%2,%3};"
        : "+f"(d[0]), "+f"(d[1]), "+f"(d[2]), "+f"(d[3])
        : "r"(a[0]), "r"(a[1]), "r"(a[2]), "r"(a[3]), "r"(b[0]), "r"(b[1]));
}

// smem tile strides (pads make fragment reads conflict-free bijections mod 32)
constexpr int AR_LD = 20;    // A row-major [128][20]: bank (20m+k)%32 distinct
constexpr int AK_LD = 136;   // A [K][M]    [16][136]: bank (8k+m)%32 distinct
constexpr int BK_LD = 136;   // B [K][N]    [16][136]
constexpr int BN_LD = 20;    // B [N][K]    [128][20]
constexpr int SM_TILE = 2560; // floats per stage buffer (max of 128*20, 16*136)

// ALAY: 0 = A stored [M][K] (K-contig), 1 = A stored [K][M] (M-contig)
// BLAY: 0 = B stored [K][N] (N-contig), 1 = B stored [N][K] (K-contig)
template<int ALAY>
DEVI void load_a_tile(float* sA, const float* A, int ldA, int k0, int tid) {
    if (ALAY == 0) {
        int m = tid >> 2;
        int kc = (tid & 3) << 2;
        cpa16(&sA[m * AR_LD + kc],        A + (size_t)m * ldA + k0 + kc);
        cpa16(&sA[(m + 64) * AR_LD + kc], A + (size_t)(m + 64) * ldA + k0 + kc);
    } else {
        int kk = tid >> 5;
        int mc = (tid & 31) << 2;
        cpa16(&sA[kk * AK_LD + mc],       A + (size_t)(k0 + kk) * ldA + mc);
        cpa16(&sA[(kk + 8) * AK_LD + mc], A + (size_t)(k0 + kk + 8) * ldA + mc);
    }
}
template<int BLAY>
DEVI void load_b_tile(float* sB, const float* B, int ldB, int k0, int tid) {
    if (BLAY == 0) {
        int kk = tid >> 5;
        int nc = (tid & 31) << 2;
        cpa16(&sB[kk * BK_LD + nc],       B + (size_t)(k0 + kk) * ldB + nc);
        cpa16(&sB[(kk + 8) * BK_LD + nc], B + (size_t)(k0 + kk + 8) * ldB + nc);
    } else {
        int n = tid >> 2;
        int kc = (tid & 3) << 2;
        cpa16(&sB[n * BN_LD + kc],        B + (size_t)n * ldB + k0 + kc);
        cpa16(&sB[(n + 64) * BN_LD + kc], B + (size_t)(n + 64) * ldB + k0 + kc);
    }
}

template<int ALAY, int BLAY>
DEVI void gemm_core(const float* A, int ldA, const float* B, int ldB, int K,
                    float (&acc)[4][4][4],
                    float (*sA)[SM_TILE], float (*sB)[SM_TILE]) {
    const int tid = threadIdx.x;
    const int warp = tid >> 5, lane = tid & 31;
    const int wm = warp >> 2, wn = warp & 3;
    const int grp = lane >> 2, tig = lane & 3;

    #pragma unroll
    for (int i = 0; i < 4; i++)
        #pragma unroll
        for (int j = 0; j < 4; j++)
            #pragma unroll
            for (int r = 0; r < 4; r++) acc[i][j][r] = 0.f;

    const int KT = K >> 4;
    load_a_tile<ALAY>(sA[0], A, ldA, 0, tid);
    load_b_tile<BLAY>(sB[0], B, ldB, 0, tid);
    cpa_commit();

    for (int kt = 0; kt < KT; ++kt) {
        if (kt + 1 < KT) {
            int nb = (kt + 1) & 1;
            load_a_tile<ALAY>(sA[nb], A, ldA, (kt + 1) << 4, tid);
            load_b_tile<BLAY>(sB[nb], B, ldB, (kt + 1) << 4, tid);
            cpa_commit();
            cpa_wait_one();
        } else {
            cpa_wait_all();
        }
        __syncthreads();
        const float* cA = sA[kt & 1];
        const float* cB = sB[kt & 1];
        #pragma unroll
        for (int ks = 0; ks < 2; ++ks) {
            uint32_t afr[4][4];
            #pragma unroll
            for (int mi = 0; mi < 4; ++mi) {
                int m0 = wm * 64 + mi * 16;
                if (ALAY == 0) {
                    int base = (m0 + grp) * AR_LD + ks * 8 + tig;
                    afr[mi][0] = __float_as_uint(cA[base]);
                    afr[mi][1] = __float_as_uint(cA[base + 8 * AR_LD]);
                    afr[mi][2] = __float_as_uint(cA[base + 4]);
                    afr[mi][3] = __float_as_uint(cA[base + 8 * AR_LD + 4]);
                } else {
                    int r0 = (ks * 8 + tig) * AK_LD + m0 + grp;
                    int r1 = (ks * 8 + tig + 4) * AK_LD + m0 + grp;
                    afr[mi][0] = __float_as_uint(cA[r0]);
                    afr[mi][1] = __float_as_uint(cA[r0 + 8]);
                    afr[mi][2] = __float_as_uint(cA[r1]);
                    afr[mi][3] = __float_as_uint(cA[r1 + 8]);
                }
            }
            uint32_t bfr[4][2];
            #pragma unroll
            for (int ni = 0; ni < 4; ++ni) {
                int n0 = wn * 32 + ni * 8;
                if (BLAY == 0) {
                    bfr[ni][0] = __float_as_uint(cB[(ks * 8 + tig) * BK_LD + n0 + grp]);
                    bfr[ni][1] = __float_as_uint(cB[(ks * 8 + tig + 4) * BK_LD + n0 + grp]);
                } else {
                    int base = (n0 + grp) * BN_LD + ks * 8 + tig;
                    bfr[ni][0] = __float_as_uint(cB[base]);
                    bfr[ni][1] = __float_as_uint(cB[base + 4]);
                }
            }
            #pragma unroll
            for (int mi = 0; mi < 4; ++mi)
                #pragma unroll
                for (int ni = 0; ni < 4; ++ni)
                    mma8(acc[mi][ni], afr[mi], bfr[ni]);
        }
        __syncthreads();
    }
}

struct BNSet { const float* g; const float* b; const float* m; const float* v; };

// ---- prep kernels: round inputs to tf32 once (rna, unbiased) ----
__global__ void prep_x_k(const float* __restrict__ x) {
    const float4* src = (const float4*)x;
    float4* dst = (float4*)g_xt;
    const int total = NB * CH * SP / 4;
    for (int i = blockIdx.x * blockDim.x + threadIdx.x; i < total;
         i += gridDim.x * blockDim.x) {
        float4 v = src[i];
        v.x = to_tf32(v.x); v.y = to_tf32(v.y);
        v.z = to_tf32(v.z); v.w = to_tf32(v.w);
        dst[i] = v;
    }
}

__global__ void prep_w_k(const float* __restrict__ wt, const float* __restrict__ wp,
                         const float* __restrict__ wg, const float* __restrict__ wz) {
    int i = blockIdx.x * blockDim.x + threadIdx.x; // grid covers exactly 131072
    const int WSZ = WD * CH; // 32768
    if (i < 3 * WSZ) {
        const float* src = (i < WSZ) ? wt : (i < 2 * WSZ) ? wp : wg;
        g_wt[i] = to_tf32(src[i % WSZ]);
    } else {
        int j = i - 3 * WSZ;
        g_wz[j] = to_tf32(wz[j]);
    }
}

// ---- stage A: TPG = relu(bn(Wcat @ x)), tf32-rounded ----
__global__ void __launch_bounds__(256, 2)
stageA_k(BNSet bn1, BNSet bn2, BNSet bn3) {
    __shared__ float sA[2][SM_TILE];
    __shared__ float sB[2][SM_TILE];
    const int st = blockIdx.x;  // s tile 0..31
    const int ot = blockIdx.y;  // 0=theta 1=phi 2=g
    const int n  = blockIdx.z;

    const float* A = g_wt + (size_t)ot * WD * CH;               // [128][256]
    const float* B = g_xt + (size_t)n * CH * SP + st * 128;     // [256][4096]
    float acc[4][4][4];
    gemm_core<0, 0>(A, CH, B, SP, CH, acc, sA, sB);

    BNSet bn = (ot == 0) ? bn1 : (ot == 1) ? bn2 : bn3;
    const int tid = threadIdx.x, warp = tid >> 5, lane = tid & 31;
    const int wm = warp >> 2, wn = warp & 3, grp = lane >> 2, tig = lane & 3;
    float* Cbase = g_TPG + (size_t)n * 3 * WD * SP + (size_t)ot * WD * SP;
    #pragma unroll
    for (int mi = 0; mi < 4; ++mi) {
        int r0 = wm * 64 + mi * 16 + grp;
        #pragma unroll
        for (int half = 0; half < 2; ++half) {
            int row = r0 + half * 8;
            float sc = bn.g[row] * rsqrtf(bn.v[row] + BN_EPS);
            float sh = bn.b[row] - bn.m[row] * sc;
            #pragma unroll
            for (int ni = 0; ni < 4; ++ni) {
                int col = st * 128 + wn * 32 + ni * 8 + tig * 2;
                float v0 = fmaxf(fmaf(acc[mi][ni][half * 2 + 0], sc, sh), 0.f);
                float v1 = fmaxf(fmaf(acc[mi][ni][half * 2 + 1], sc, sh), 0.f);
                *reinterpret_cast<float2*>(&Cbase[(size_t)row * SP + col]) =
                    make_float2(to_tf32(v0), to_tf32(v1));
            }
        }
    }
}

// ---- stage B: kv partials (split-K), raw fp32 ----
__global__ void __launch_bounds__(256, 2)
stageB_k() {
    __shared__ float sA[2][SM_TILE];
    __shared__ float sB[2][SM_TILE];
    const int ck = blockIdx.x;  // K chunk 0..7
    const int n  = blockIdx.z;
    const float* A = g_TPG + (size_t)n * 3 * WD * SP + (size_t)WD * SP     + ck * KVCHUNK; // phi [c][s]
    const float* B = g_TPG + (size_t)n * 3 * WD * SP + (size_t)2 * WD * SP + ck * KVCHUNK; // g   [d][s]
    float acc[4][4][4];
    gemm_core<0, 1>(A, SP, B, SP, KVCHUNK, acc, sA, sB);

    const int tid = threadIdx.x, warp = tid >> 5, lane = tid & 31;
    const int wm = warp >> 2, wn = warp & 3, grp = lane >> 2, tig = lane & 3;
    float* Cbase = g_kvp + ((size_t)n * KVSPLIT + ck) * WD * WD;
    #pragma unroll
    for (int mi = 0; mi < 4; ++mi)
        #pragma unroll
        for (int half = 0; half < 2; ++half) {
            int row = wm * 64 + mi * 16 + grp + half * 8;
            #pragma unroll
            for (int ni = 0; ni < 4; ++ni) {
                int col = wn * 32 + ni * 8 + tig * 2;
                *reinterpret_cast<float2*>(&Cbase[(size_t)row * WD + col]) =
                    make_float2(acc[mi][ni][half * 2], acc[mi][ni][half * 2 + 1]);
            }
        }
}

__global__ void kv_reduce_k() {
    int i = blockIdx.x * blockDim.x + threadIdx.x; // grid covers 262144 exactly
    int n = i >> 14;
    int rem = i & 16383;
    float s = 0.f;
    #pragma unroll
    for (int j = 0; j < KVSPLIT; ++j)
        s += g_kvp[((size_t)n * KVSPLIT + j) * (WD * WD) + rem];
    g_kv[i] = to_tf32(s);
}

// ---- stage C: O[s,d] = sum_c T[c,s] * kv[c,d]; stored flat s*128+d ----
__global__ void __launch_bounds__(256, 2)
stageC_k() {
    __shared__ float sA[2][SM_TILE];
    __shared__ float sB[2][SM_TILE];
    const int mt = blockIdx.x;  // s tile 0..31
    const int n  = blockIdx.z;
    const float* A = g_TPG + (size_t)n * 3 * WD * SP + mt * 128; // theta [K=c][M=s], ld=SP
    const float* B = g_kv + (size_t)n * WD * WD;                 // kv [K=c][N=d], ld=WD
    float acc[4][4][4];
    gemm_core<1, 0>(A, SP, B, WD, WD, acc, sA, sB);

    const int tid = threadIdx.x, warp = tid >> 5, lane = tid & 31;
    const int wm = warp >> 2, wn = warp & 3, grp = lane >> 2, tig = lane & 3;
    float* Cbase = g_O + (size_t)n * SP * WD + (size_t)mt * 128 * WD;
    #pragma unroll
    for (int mi = 0; mi < 4; ++mi)
        #pragma unroll
        for (int half = 0; half < 2; ++half) {
            int row = wm * 64 + mi * 16 + grp + half * 8;
            #pragma unroll
            for (int ni = 0; ni < 4; ++ni) {
                int col = wn * 32 + ni * 8 + tig * 2;
                *reinterpret_cast<float2*>(&Cbase[(size_t)row * WD + col]) =
                    make_float2(to_tf32(acc[mi][ni][half * 2]),
                                to_tf32(acc[mi][ni][half * 2 + 1]));
            }
        }
}

// ---- stage D: out = relu(bn4(Wzeta @ Y) + x) ----
__global__ void __launch_bounds__(256, 2)
stageD_k(const float* __restrict__ x, float* __restrict__ out, BNSet bn4) {
    __shared__ float sA[2][SM_TILE];
    __shared__ float sB[2][SM_TILE];
    const int pt = blockIdx.x;  // p tile 0..31
    const int ot = blockIdx.y;  // 0..1
    const int n  = blockIdx.z;
    const float* A = g_wz + (size_t)ot * 128 * WD;           // [128][128], ld=WD
    const float* B = g_O + (size_t)n * SP * WD + pt * 128;   // Y [K=128][N=4096], ld=SP
    float acc[4][4][4];
    gemm_core<0, 0>(A, WD, B, SP, WD, acc, sA, sB);

    const int tid = threadIdx.x, warp = tid >> 5, lane = tid & 31;
    const int wm = warp >> 2, wn = warp & 3, grp = lane >> 2, tig = lane & 3;
    #pragma unroll
    for (int mi = 0; mi < 4; ++mi)
        #pragma unroll
        for (int half = 0; half < 2; ++half) {
            int o = ot * 128 + wm * 64 + mi * 16 + grp + half * 8;
            float sc = bn4.g[o] * rsqrtf(bn4.v[o] + BN_EPS);
            float sh = bn4.b[o] - bn4.m[o] * sc;
            #pragma unroll
            for (int ni = 0; ni < 4; ++ni) {
                int col = pt * 128 + wn * 32 + ni * 8 + tig * 2;
                size_t idx = (size_t)n * CH * SP + (size_t)o * SP + col;
                float2 xv = *reinterpret_cast<const float2*>(&x[idx]);
                float v0 = fmaxf(fmaf(acc[mi][ni][half * 2 + 0], sc, sh) + xv.x, 0.f);
                float v1 = fmaxf(fmaf(acc[mi][ni][half * 2 + 1], sc, sh) + xv.y, 0.f);
                *reinterpret_cast<float2*>(&out[idx]) = make_float2(v0, v1);
            }
        }
}

extern "C" void kernel_launch(void* const* d_in, const int* in_sizes, int n_in,
                              void* d_out, int out_size) {
    const float* x       = (const float*)d_in[0];
    const float* w_theta = (const float*)d_in[1];
    const float* w_phi   = (const float*)d_in[2];
    const float* w_g     = (const float*)d_in[3];
    const float* w_zeta  = (const float*)d_in[4];
    BNSet bn1{(const float*)d_in[5],  (const float*)d_in[6],
              (const float*)d_in[7],  (const float*)d_in[8]};
    BNSet bn2{(const float*)d_in[9],  (const float*)d_in[10],
              (const float*)d_in[11], (const float*)d_in[12]};
    BNSet bn3{(const float*)d_in[13], (const float*)d_in[14],
              (const float*)d_in[15], (const float*)d_in[16]};
    BNSet bn4{(const float*)d_in[17], (const float*)d_in[18],
              (const float*)d_in[19], (const float*)d_in[20]};
    float* out = (float*)d_out;

    prep_x_k<<<4096, 256>>>(x);
    prep_w_k<<<512, 256>>>(w_theta, w_phi, w_g, w_zeta);       // 512*256 == 131072 exactly
    stageA_k<<<dim3(32, 3, NB), 256>>>(bn1, bn2, bn3);
    stageB_k<<<dim3(KVSPLIT, 1, NB), 256>>>();
    kv_reduce_k<<<1024, 256>>>();                              // 1024*256 == 262144 exactly
    stageC_k<<<dim3(32, 1, NB), 256>>>();
    stageD_k<<<dim3(32, 2, NB), 256>>>(x, out, bn4);
}